// round 5
// baseline (speedup 1.0000x reference)
#include <cuda_runtime.h>
#include <cstdint>

// Problem constants
#define NB    16
#define CC    256
#define MM    63
#define MO    56
#define CSPL  8
#define CPER  32                 // channels per block
#define OUTSZ (NB * MO * MO)     // 50176
#define XCH   (MM * MM)          // 3969 floats per (n,c) x-plane
#define SQST  64                 // padded row stride of sqrt tile
#define SQSZ  (MM * SQST)        // 4032 floats
#define RAWSZ 3972               // raw buffer (3969 used, padded)

typedef unsigned long long ull;

// Channel-split partials; fully rewritten every launch (deterministic).
__device__ float g_partial[CSPL * OUTSZ];

// ---------- helpers ----------
static __device__ __forceinline__ float fsqrt_approx(float a) {
    float r; asm("sqrt.approx.f32 %0, %1;" : "=f"(r) : "f"(a)); return r;
}
static __device__ __forceinline__ ull pk(float lo, float hi) {
    ull r;
    asm("mov.b64 %0, {%1, %2};" : "=l"(r)
        : "r"(__float_as_uint(lo)), "r"(__float_as_uint(hi)));
    return r;
}
static __device__ __forceinline__ ull f2fma(ull a, ull b, ull c) {
    ull d;
    asm("fma.rn.f32x2 %0, %1, %2, %3;" : "=l"(d) : "l"(a), "l"(b), "l"(c));
    return d;
}
static __device__ __forceinline__ void cpa4(uint32_t d, const void* s) {
    asm volatile("cp.async.ca.shared.global [%0], [%1], 4;" :: "r"(d), "l"(s));
}
static __device__ __forceinline__ void cpa16(uint32_t d, const void* s) {
    asm volatile("cp.async.ca.shared.global [%0], [%1], 16;" :: "r"(d), "l"(s));
}
#define CPCOMMIT() asm volatile("cp.async.commit_group;")
#define CPWAIT(n)  asm volatile("cp.async.wait_group %0;" :: "n"(n))

// Build the 8 overlapping column pairs for one sqrt(x) row (floats base..base+9).
// 5 conflict-free LDS.64 + 4 packs.
static __device__ __forceinline__ void loadrow(ull* d, const float* base) {
    float2 a0 = *(const float2*)(base + 0);
    float2 a1 = *(const float2*)(base + 2);
    float2 a2 = *(const float2*)(base + 4);
    float2 a3 = *(const float2*)(base + 6);
    float2 a4 = *(const float2*)(base + 8);
    d[0] = pk(a0.x, a0.y);  d[2] = pk(a1.x, a1.y);
    d[4] = pk(a2.x, a2.y);  d[6] = pk(a3.x, a3.y);
    d[1] = pk(a0.y, a1.x);  d[3] = pk(a1.y, a2.x);
    d[5] = pk(a2.y, a3.x);  d[7] = pk(a3.y, a4.x);
}

// ---------- main kernel ----------
// grid = 16 n x 8 cs = 128 blocks of 256 threads (8 warps).
// Warp w owns output rows [7w, 7w+7); lane u<28 owns output cols (2u, 2u+1).
// Per channel: cp.async-prefetched raw tile -> sqrt convert -> register-window
// f32x2 cross-correlation. Accumulators persist across the 32 channels.
__global__ __launch_bounds__(256)
void bc_main(const float* __restrict__ z, const float* __restrict__ x,
             const float* __restrict__ w) {
    extern __shared__ float sm[];
    float* SQ0 = sm;
    float* SQ1 = sm + SQSZ;
    float* RW0 = sm + 2 * SQSZ;
    float* RW1 = RW0 + RAWSZ;
    ull*   ZW0 = (ull*)(RW1 + RAWSZ);
    ull*   ZW1 = ZW0 + 64;
    float* RZ0 = (float*)(ZW1 + 64);
    float* RZ1 = RZ0 + 64;
    float* SW  = RZ1 + 64;           // 32 per-channel weights

    const int bid  = blockIdx.x;
    const int cs   = bid & 7;
    const int n    = bid >> 3;
    const int t    = threadIdx.x;
    const int wid  = t >> 5;
    const int lane = t & 31;
    const bool act = lane < 28;
    const int RB = wid * 7;
    const int CB = 2 * lane;

    const float* xb = x + ((size_t)(n * CC + cs * CPER)) * XCH;
    const float* zb = z + ((size_t)(n * CC + cs * CPER)) * 64;

    const uint32_t rwA[2] = { (uint32_t)__cvta_generic_to_shared(RW0),
                              (uint32_t)__cvta_generic_to_shared(RW1) };
    const uint32_t rzA[2] = { (uint32_t)__cvta_generic_to_shared(RZ0),
                              (uint32_t)__cvta_generic_to_shared(RZ1) };
    float* SQp[2] = {SQ0, SQ1};
    const float* RWp[2] = {RW0, RW1};
    ull* ZWp[2] = {ZW0, ZW1};
    const float* RZp[2] = {RZ0, RZ1};

    if (t < 32) SW[t] = __ldg(w + cs * CPER + t);

    // Prologue: prefetch channels 0 and 1 (one cp.async group each).
    {
        const float* xc = xb;
        #pragma unroll
        for (int j = 0; j < 16; ++j) {
            int i = t + 256 * j;
            if (i < XCH) cpa4(rwA[0] + 4u * i, xc + i);
        }
        if (t < 16) cpa16(rzA[0] + 16u * t, zb + 4 * t);
        CPCOMMIT();
        const float* xc1 = xb + XCH;
        #pragma unroll
        for (int j = 0; j < 16; ++j) {
            int i = t + 256 * j;
            if (i < XCH) cpa4(rwA[1] + 4u * i, xc1 + i);
        }
        if (t < 16) cpa16(rzA[1] + 16u * t, zb + 64 + 4 * t);
        CPCOMMIT();
    }
    __syncthreads();            // publish SW
    CPWAIT(1);                  // channel 0 landed
    // Convert channel 0 (each thread reads only its own copied slice).
    {
        #pragma unroll
        for (int j = 0; j < 16; ++j) {
            int i = t + 256 * j;
            if (i < XCH) {
                int r = i / 63, c2 = i - r * 63;
                SQ0[r * SQST + c2] = fsqrt_approx(RW0[i]);
            }
        }
        if (t < 16) {
            float wc = SW[0] * (1.0f / 64.0f);
            #pragma unroll
            for (int e = 0; e < 4; ++e) {
                float v = wc * fsqrt_approx(RZ0[4 * t + e]);
                ZW0[4 * t + e] = pk(v, v);
            }
        }
    }

    ull acc[7];
    #pragma unroll
    for (int r = 0; r < 7; ++r) acc[r] = 0ull;

    #pragma unroll 1
    for (int c = 0; c < CPER; ++c) {
        __syncthreads();   // publishes SQ/ZW of channel c; frees last iter's buffers

        if (c + 1 < CPER) {
            CPWAIT(0);                         // channel c+1 raw landed
            const int b = (c + 1) & 1;
            float* SQd = SQp[b];
            const float* RWs = RWp[b];
            #pragma unroll
            for (int j = 0; j < 16; ++j) {
                int i = t + 256 * j;
                if (i < XCH) {
                    int r = i / 63, c2 = i - r * 63;
                    SQd[r * SQST + c2] = fsqrt_approx(RWs[i]);
                }
            }
            if (t < 16) {
                float wc = SW[c + 1] * (1.0f / 64.0f);
                const float* RZs = RZp[b];
                ull* ZWd = ZWp[b];
                #pragma unroll
                for (int e = 0; e < 4; ++e) {
                    float v = wc * fsqrt_approx(RZs[4 * t + e]);
                    ZWd[4 * t + e] = pk(v, v);
                }
            }
            if (c + 2 < CPER) {                // prefetch channel c+2 into freed buffer
                const int b2 = c & 1;
                const float* xc = xb + (size_t)(c + 2) * XCH;
                #pragma unroll
                for (int j = 0; j < 16; ++j) {
                    int i = t + 256 * j;
                    if (i < XCH) cpa4(rwA[b2] + 4u * i, xc + i);
                }
                if (t < 16) cpa16(rzA[b2] + 16u * t, zb + (c + 2) * 64 + 4 * t);
                CPCOMMIT();
            }
        }

        if (act) {
            const float* S = SQp[c & 1] + RB * SQST + CB;
            const ull*   Z = ZWp[c & 1];
            ull W[7][8];                       // rolling 7-row window of pairs
            #pragma unroll
            for (int r0 = 0; r0 < 6; ++r0) loadrow(W[r0], S + r0 * SQST);
            #pragma unroll
            for (int p = 0; p < 8; ++p) {
                loadrow(W[(p + 6) % 7], S + (p + 6) * SQST);
                ulonglong2 z01 = *(const ulonglong2*)(Z + 8 * p + 0);
                ulonglong2 z23 = *(const ulonglong2*)(Z + 8 * p + 2);
                ulonglong2 z45 = *(const ulonglong2*)(Z + 8 * p + 4);
                ulonglong2 z67 = *(const ulonglong2*)(Z + 8 * p + 6);
                const ull zq[8] = {z01.x, z01.y, z23.x, z23.y,
                                   z45.x, z45.y, z67.x, z67.y};
                #pragma unroll
                for (int r = 0; r < 7; ++r) {
                    ull* Wr = W[(p + r) % 7];
                    #pragma unroll
                    for (int q = 0; q < 8; ++q)
                        acc[r] = f2fma(Wr[q], zq[q], acc[r]);
                }
            }
        }
    }

    if (act) {
        float* dst = g_partial + (size_t)cs * OUTSZ + n * (MO * MO);
        #pragma unroll
        for (int r = 0; r < 7; ++r)
            *(ull*)(dst + (RB + r) * MO + CB) = acc[r];   // STG.64, CB even
    }
}

// ---------- reduction: sum the 8 channel-split partials (float4) ----------
__global__ void bc_reduce(float* __restrict__ out) {
    const int i = blockIdx.x * blockDim.x + threadIdx.x;   // i < OUTSZ/4
    if (i < OUTSZ / 4) {
        const float4* gp = (const float4*)g_partial;
        float4 s = gp[i];
        #pragma unroll
        for (int k = 1; k < CSPL; ++k) {
            float4 v = gp[(size_t)k * (OUTSZ / 4) + i];
            s.x += v.x; s.y += v.y; s.z += v.z; s.w += v.w;
        }
        ((float4*)out)[i] = s;
    }
}

// ---------- launch ----------
extern "C" void kernel_launch(void* const* d_in, const int* in_sizes, int n_in,
                              void* d_out, int out_size) {
    const float* z = (const float*)d_in[0];   // (16,256,8,8)
    const float* x = (const float*)d_in[1];   // (16,256,63,63)
    const float* w = (const float*)d_in[2];   // 256 weights
    float* out = (float*)d_out;               // (16,1,56,56)

    const int smem = (2 * SQSZ + 2 * RAWSZ) * 4 + 2 * 64 * 8 + 2 * 64 * 4 + 32 * 4;
    cudaFuncSetAttribute(bc_main, cudaFuncAttributeMaxDynamicSharedMemorySize, smem);
    bc_main<<<NB * CSPL, 256, smem>>>(z, x, w);
    bc_reduce<<<(OUTSZ / 4 + 255) / 256, 256>>>(out);
}

// round 6
// speedup vs baseline: 1.1631x; 1.1631x over previous
#include <cuda_runtime.h>
#include <cstdint>

// Problem constants
#define NB    16
#define CC    256
#define MM    63
#define MO    56
#define CSPL  8
#define CPER  32                  // channels per block
#define OUTSZ (NB * MO * MO)      // 50176
#define XCH   (MM * MM)           // 3969 floats per (n,c) plane
#define SQST  64                  // padded row stride of sqrt tile

typedef unsigned long long ull;

// Channel-split partials; fully rewritten every launch (deterministic).
__device__ float g_partial[CSPL * OUTSZ];

// ---------- helpers ----------
static __device__ __forceinline__ float fsqrt_approx(float a) {
    float r; asm("sqrt.approx.f32 %0, %1;" : "=f"(r) : "f"(a)); return r;
}
static __device__ __forceinline__ ull pk(float lo, float hi) {
    ull r;
    asm("mov.b64 %0, {%1, %2};" : "=l"(r)
        : "r"(__float_as_uint(lo)), "r"(__float_as_uint(hi)));
    return r;
}
static __device__ __forceinline__ ull f2fma(ull a, ull b, ull c) {
    ull d;
    asm("fma.rn.f32x2 %0, %1, %2, %3;" : "=l"(d) : "l"(a), "l"(b), "l"(c));
    return d;
}
// Load 6 floats (b..b+5) as 3 conflict-free LDS.64; build 4 overlapping pairs.
static __device__ __forceinline__ void load4(ull* d, const float* b) {
    float2 a0 = *(const float2*)(b + 0);
    float2 a1 = *(const float2*)(b + 2);
    float2 a2 = *(const float2*)(b + 4);
    d[0] = pk(a0.x, a0.y);
    d[1] = pk(a0.y, a1.x);
    d[2] = pk(a1.x, a1.y);
    d[3] = pk(a1.y, a2.x);
}

// ---------- main kernel ----------
// grid = 16 n x 8 cs = 128 blocks of 256 threads (8 warps).
// Warp w owns output rows [7w, 7w+7); lane u<28 owns output cols (2u, 2u+1).
// One (n,cs) block covers all 56x56 outputs over its 32 channels, staging each
// x-plane exactly once. Register-double-buffered LDG prefetch, one barrier per
// channel, f32x2 FMA with a 7-row rolling window split into two 4-tap q-halves.
__global__ __launch_bounds__(256)
void bc_main(const float* __restrict__ z, const float* __restrict__ x,
             const float* __restrict__ w) {
    __shared__ float SQ0[4096];               // sqrt tiles, 63 rows x 64 (padded)
    __shared__ float SQ1[4096];
    __shared__ __align__(16) ull ZW0[64];     // splatted w*sqrt(z)/64 pairs
    __shared__ __align__(16) ull ZW1[64];

    const int bid  = blockIdx.x;
    const int cs   = bid & 7;
    const int n    = bid >> 3;
    const int t    = threadIdx.x;
    const int wid  = t >> 5;
    const int lane = t & 31;
    const bool act = lane < 28;
    const int RB = wid * 7;
    const int CB = 2 * lane;

    const float* xb = x + ((size_t)(n * CC + cs * CPER)) * XCH;
    const float* zb = z + ((size_t)(n * CC + cs * CPER)) * 64;
    const float* wp = w + cs * CPER;

    // Staging offsets in padded space: ip = t+256k -> src = ip - ip/64,
    // clamped so the col-63 padding lanes read a safe in-plane address.
    int offs[16];
    #pragma unroll
    for (int k = 0; k < 16; ++k) {
        int ip = t + 256 * k;
        int g  = ip - (ip >> 6);
        offs[k] = g < 3968 ? g : 3968;
    }

    float rx[16];
    float zrx = 0.0f;

    // ---- prologue: load+convert ch0, prefetch ch1 ----
    #pragma unroll
    for (int k = 0; k < 16; ++k) rx[k] = __ldg(xb + offs[k]);
    if (t < 64) zrx = __ldg(zb + t);
    #pragma unroll
    for (int k = 0; k < 16; ++k) SQ0[t + 256 * k] = fsqrt_approx(rx[k]);
    if (t < 64) {
        float wc = __ldg(wp) * (1.0f / 64.0f);
        float v  = wc * fsqrt_approx(zrx);
        ZW0[t] = pk(v, v);
    }
    #pragma unroll
    for (int k = 0; k < 16; ++k) rx[k] = __ldg(xb + XCH + offs[k]);
    if (t < 64) zrx = __ldg(zb + 64 + t);

    ull acc[7];
    #pragma unroll
    for (int r = 0; r < 7; ++r) acc[r] = 0ull;

    #pragma unroll 1
    for (int c = 0; c < CPER; ++c) {
        __syncthreads();   // SQ/ZW of channel c published; prev reads retired

        if (c + 1 < CPER) {
            // convert prefetched channel c+1 into the other buffer
            float* SQd = ((c + 1) & 1) ? SQ1 : SQ0;
            #pragma unroll
            for (int k = 0; k < 16; ++k)
                SQd[t + 256 * k] = fsqrt_approx(rx[k]);
            if (t < 64) {
                float wc = __ldg(wp + c + 1) * (1.0f / 64.0f);
                float v  = wc * fsqrt_approx(zrx);
                (((c + 1) & 1) ? ZW1 : ZW0)[t] = pk(v, v);
            }
            if (c + 2 < CPER) {               // prefetch raw channel c+2
                const float* xs = xb + (size_t)(c + 2) * XCH;
                #pragma unroll
                for (int k = 0; k < 16; ++k) rx[k] = __ldg(xs + offs[k]);
                if (t < 64) zrx = __ldg(zb + (c + 2) * 64 + t);
            }
        }

        if (act) {
            const float* S = ((c & 1) ? SQ1 : SQ0) + RB * SQST + CB;
            const ull*   Z = (c & 1) ? ZW1 : ZW0;

            // ---- q-half 0: taps q=0..3 ----
            {
                ull W[7][4];
                #pragma unroll
                for (int r0 = 0; r0 < 6; ++r0) load4(W[r0], S + r0 * SQST);
                #pragma unroll
                for (int p = 0; p < 8; ++p) {
                    load4(W[(p + 6) % 7], S + (p + 6) * SQST);
                    ulonglong2 za = *(const ulonglong2*)(Z + 8 * p + 0);
                    ulonglong2 zc = *(const ulonglong2*)(Z + 8 * p + 2);
                    #pragma unroll
                    for (int r = 0; r < 7; ++r) {
                        ull* Wr = W[(p + r) % 7];
                        acc[r] = f2fma(Wr[0], za.x, acc[r]);
                        acc[r] = f2fma(Wr[1], za.y, acc[r]);
                        acc[r] = f2fma(Wr[2], zc.x, acc[r]);
                        acc[r] = f2fma(Wr[3], zc.y, acc[r]);
                    }
                }
            }
            // ---- q-half 1: taps q=4..7 (same structure, shifted 4 cols) ----
            {
                ull W[7][4];
                #pragma unroll
                for (int r0 = 0; r0 < 6; ++r0) load4(W[r0], S + 4 + r0 * SQST);
                #pragma unroll
                for (int p = 0; p < 8; ++p) {
                    load4(W[(p + 6) % 7], S + 4 + (p + 6) * SQST);
                    ulonglong2 za = *(const ulonglong2*)(Z + 8 * p + 4);
                    ulonglong2 zc = *(const ulonglong2*)(Z + 8 * p + 6);
                    #pragma unroll
                    for (int r = 0; r < 7; ++r) {
                        ull* Wr = W[(p + r) % 7];
                        acc[r] = f2fma(Wr[0], za.x, acc[r]);
                        acc[r] = f2fma(Wr[1], za.y, acc[r]);
                        acc[r] = f2fma(Wr[2], zc.x, acc[r]);
                        acc[r] = f2fma(Wr[3], zc.y, acc[r]);
                    }
                }
            }
        }
    }

    if (act) {
        float* dst = g_partial + (size_t)cs * OUTSZ + n * (MO * MO);
        #pragma unroll
        for (int r = 0; r < 7; ++r)
            *(ull*)(dst + (RB + r) * MO + CB) = acc[r];   // STG.64, CB even
    }
}

// ---------- reduction: sum the 8 channel-split partials (float4) ----------
// 12544 float4 outputs = 196 blocks x 64 threads, exact.
__global__ __launch_bounds__(64)
void bc_reduce(float* __restrict__ out) {
    const int i = blockIdx.x * 64 + threadIdx.x;
    const float4* gp = (const float4*)g_partial;
    float4 s = gp[i];
    #pragma unroll
    for (int k = 1; k < CSPL; ++k) {
        float4 v = gp[(size_t)k * (OUTSZ / 4) + i];
        s.x += v.x; s.y += v.y; s.z += v.z; s.w += v.w;
    }
    ((float4*)out)[i] = s;
}

// ---------- launch ----------
extern "C" void kernel_launch(void* const* d_in, const int* in_sizes, int n_in,
                              void* d_out, int out_size) {
    const float* z = (const float*)d_in[0];   // (16,256,8,8)
    const float* x = (const float*)d_in[1];   // (16,256,63,63)
    const float* w = (const float*)d_in[2];   // 256 weights
    float* out = (float*)d_out;               // (16,1,56,56)

    bc_main<<<NB * CSPL, 256>>>(z, x, w);
    bc_reduce<<<OUTSZ / 4 / 64, 64>>>(out);
}

// round 14
// speedup vs baseline: 2.3435x; 2.0149x over previous
#include <cuda_runtime.h>
#include <cstdint>

// ---- problem constants ----
#define NB   16
#define CC   256
#define MM   63
#define MO   56
#define XPL  3969            // 63*63 floats per (n,c) plane
#define PX   4096            // padded pixel space (64x64) per sample
#define NTAP 64
#define MT   32              // 32 m-tiles of 128 pixels

// smem word layout: A frags [8 warptiles][16 kk][32 lane][4 reg] = 16384 words (64KB)
//                   B frags [16 kk][8 nf][32 lane][2 reg]       =  8192 words (32KB)
#define BBASE 16384
#define SMEMB ((16384 + 8192) * 4)       // 98304 bytes
#define DSTR  65                          // D smem row stride (floats)

// D^T scratch: [n][tap][pixel] fp32 = 16 MB, fully rewritten each launch.
__device__ float g_dt[(size_t)NB * NTAP * PX];

static __device__ __forceinline__ float fsq(float a) {
    float r; asm("sqrt.approx.f32 %0, %1;" : "=f"(r) : "f"(a)); return r;
}
// pack: low half = lo, high half = hi (cvt puts %1 in upper 16 bits)
static __device__ __forceinline__ uint32_t bpk(float lo, float hi) {
    uint32_t r;
    asm("cvt.rn.bf16x2.f32 %0, %1, %2;" : "=r"(r) : "f"(hi), "f"(lo));
    return r;
}
static __device__ __forceinline__ void mma16816(float* d, uint4 a, uint2 b) {
    asm volatile(
        "mma.sync.aligned.m16n8k16.row.col.f32.bf16.bf16.f32 "
        "{%0,%1,%2,%3}, {%4,%5,%6,%7}, {%8,%9}, {%0,%1,%2,%3};"
        : "+f"(d[0]), "+f"(d[1]), "+f"(d[2]), "+f"(d[3])
        : "r"(a.x), "r"(a.y), "r"(a.z), "r"(a.w), "r"(b.x), "r"(b.y));
}

// ============================================================
// GEMM: per sample n, D[pixel 4096][tap 64] = sum_c sqrt(x[c,pix]) *
//       (w[c]*sqrt(z[c,tap])/64), bf16 in / fp32 accum, via mma.sync.
// grid (32 mtiles, 16 n), 256 threads (8 warps; warp w owns 16 pixels).
// ============================================================
__global__ __launch_bounds__(256)
void bc_gemm(const float* __restrict__ z, const float* __restrict__ x,
             const float* __restrict__ w) {
    extern __shared__ uint32_t sm4[];
    const int u   = threadIdx.x;
    const int ell = u & 31, grp = u >> 5;        // lane, warp
    const int rl  = ell >> 2, cq = ell & 3;      // fragment row-low / col-quad
    const int mtile = blockIdx.x, n = blockIdx.y;

    const float* xn = x + (size_t)n * CC * XPL;
    const float* zn = z + (size_t)n * CC * 64;

    // ---- stage A in fragment layout (this thread feeds mma lane 'ell' of warp 'grp') ----
    {
        const int P0  = mtile * 128 + grp * 16;
        const int pxa = P0 + rl, pxb = pxa + 8;
        const int ra = pxa >> 6, sa = pxa & 63;
        const int rb = pxb >> 6, sb = pxb & 63;
        const bool va = (sa < 63) && (ra < 63);
        const bool vb = (sb < 63) && (rb < 63);
        const int pa = (ra < 63 ? ra : 62) * 63 + (sa < 63 ? sa : 62);
        const int pb = (rb < 63 ? rb : 62) * 63 + (sb < 63 ? sb : 62);
        uint32_t* adst = sm4 + grp * 2048 + ell * 4;

        #pragma unroll 4
        for (int kk = 0; kk < 16; ++kk) {
            const float* x0 = xn + (kk * 16 + cq * 2) * XPL;
            float a0 = __ldg(x0 + pa),            a1 = __ldg(x0 + XPL + pa);
            float b0 = __ldg(x0 + pb),            b1 = __ldg(x0 + XPL + pb);
            float a8 = __ldg(x0 + 8 * XPL + pa),  a9 = __ldg(x0 + 9 * XPL + pa);
            float b8 = __ldg(x0 + 8 * XPL + pb),  b9 = __ldg(x0 + 9 * XPL + pb);
            a0 = va ? fsq(a0) : 0.f;  a1 = va ? fsq(a1) : 0.f;
            a8 = va ? fsq(a8) : 0.f;  a9 = va ? fsq(a9) : 0.f;
            b0 = vb ? fsq(b0) : 0.f;  b1 = vb ? fsq(b1) : 0.f;
            b8 = vb ? fsq(b8) : 0.f;  b9 = vb ? fsq(b9) : 0.f;
            uint4 v;
            v.x = bpk(a0, a1);   // reg0: row rl,   cols c0,c0+1
            v.y = bpk(b0, b1);   // reg1: row rl+8
            v.z = bpk(a8, a9);   // reg2: row rl,   cols c0+8,c0+9
            v.w = bpk(b8, b9);   // reg3: row rl+8
            *(uint4*)(adst + kk * 128) = v;    // STS.128, conflict-free
        }
    }
    // ---- stage B in fragment layout: warp grp = n-frag grp, lane = tap/k slot ----
    {
        const int tap = grp * 8 + rl;
        const float* zt = zn + tap;
        #pragma unroll 4
        for (int kk = 0; kk < 16; ++kk) {
            const int c0 = kk * 16 + cq * 2;
            float v0 = __ldg(w + c0)     * 0.015625f * fsq(__ldg(zt + c0 * 64));
            float v1 = __ldg(w + c0 + 1) * 0.015625f * fsq(__ldg(zt + (c0 + 1) * 64));
            float v8 = __ldg(w + c0 + 8) * 0.015625f * fsq(__ldg(zt + (c0 + 8) * 64));
            float v9 = __ldg(w + c0 + 9) * 0.015625f * fsq(__ldg(zt + (c0 + 9) * 64));
            uint2 bv;
            bv.x = bpk(v0, v1);   // reg0: k = 2cq, 2cq+1
            bv.y = bpk(v8, v9);   // reg1: k = 2cq+8, 2cq+9
            *(uint2*)(sm4 + BBASE + ((kk * 8 + grp) * 32 + ell) * 2) = bv; // STS.64
        }
    }
    __syncthreads();

    // ---- MMA mainloop: 16 k-steps x 8 n-frags ----
    float acc[8][4];
    #pragma unroll
    for (int f = 0; f < 8; ++f)
        #pragma unroll
        for (int e = 0; e < 4; ++e) acc[f][e] = 0.f;
    {
        const uint32_t* aw = sm4 + grp * 2048 + ell * 4;
        const uint32_t* bw = sm4 + BBASE + ell * 2;
        #pragma unroll
        for (int kk = 0; kk < 16; ++kk) {
            uint4 a = *(const uint4*)(aw + kk * 128);        // LDS.128, conflict-free
            #pragma unroll
            for (int nf = 0; nf < 8; ++nf) {
                uint2 b = *(const uint2*)(bw + (kk * 8 + nf) * 64);  // LDS.64
                mma16816(acc[nf], a, b);
            }
        }
    }
    __syncthreads();   // A region dead; reuse as D tile

    // ---- D frags -> smem [px 128][tap 64] (stride 65) ----
    {
        float* ds = (float*)sm4;
        const int pxl = grp * 16 + rl;
        const int t0  = 2 * cq;
        #pragma unroll
        for (int nf = 0; nf < 8; ++nf) {
            const int tw = nf * 8 + t0;
            ds[pxl * DSTR + tw]           = acc[nf][0];
            ds[pxl * DSTR + tw + 1]       = acc[nf][1];
            ds[(pxl + 8) * DSTR + tw]     = acc[nf][2];
            ds[(pxl + 8) * DSTR + tw + 1] = acc[nf][3];
        }
    }
    __syncthreads();

    // ---- transposed, coalesced store: g_dt[n][tap][mtile*128 + px] ----
    {
        const float* ds = (const float*)sm4;
        const int px = u & 127, th = u >> 7;
        float* dt = g_dt + (size_t)n * NTAP * PX + mtile * 128 + px;
        #pragma unroll 8
        for (int c = 0; c < 32; ++c) {
            const int tap = th * 32 + c;
            dt[(size_t)tap * PX] = ds[px * DSTR + tap];   // LDS conflict-free, STG coalesced
        }
    }
}

// ============================================================
// Epilogue: out[n,i,j] = sum_{p,q} D^T[n][p*8+q][(i+p)*64 + (j+q)]
// grid (56, 16), 64 threads (56 active). g_dt is L2-resident (16 MB).
// ============================================================
__global__ __launch_bounds__(64)
void bc_epi(float* __restrict__ out) {
    const int i = blockIdx.x, n = blockIdx.y, j = threadIdx.x;
    if (j >= MO) return;
    const float* dn = g_dt + (size_t)n * NTAP * PX;
    float s0 = 0.f, s1 = 0.f, s2 = 0.f, s3 = 0.f;
    #pragma unroll
    for (int p = 0; p < 8; ++p) {
        const float* row = dn + (size_t)(p * 8) * PX + ((i + p) << 6) + j;
        s0 += row[0 * PX + 0];  s1 += row[1 * PX + 1];
        s2 += row[2 * PX + 2];  s3 += row[3 * PX + 3];
        s0 += row[4 * PX + 4];  s1 += row[5 * PX + 5];
        s2 += row[6 * PX + 6];  s3 += row[7 * PX + 7];
    }
    out[((size_t)n * MO + i) * MO + j] = (s0 + s1) + (s2 + s3);
}

// Profiling pad: 5 launches/call puts bc_gemm (call 2, launch idx 5) under
// ncu's "-s 5 -c 1". Remove once tuned.
__global__ void bc_nop() {}

// ---------- launch ----------
extern "C" void kernel_launch(void* const* d_in, const int* in_sizes, int n_in,
                              void* d_out, int out_size) {
    const float* z = (const float*)d_in[0];   // (16,256,8,8)
    const float* x = (const float*)d_in[1];   // (16,256,63,63)
    const float* w = (const float*)d_in[2];   // 256 weights
    float* out = (float*)d_out;               // (16,1,56,56)

    cudaFuncSetAttribute(bc_gemm, cudaFuncAttributeMaxDynamicSharedMemorySize, SMEMB);
    bc_gemm<<<dim3(MT, NB), 256, SMEMB>>>(z, x, w);
    bc_epi<<<dim3(MO, NB), 64>>>(out);
    bc_nop<<<1, 1>>>();
    bc_nop<<<1, 1>>>();
    bc_nop<<<1, 1>>>();
}

// round 15
// speedup vs baseline: 2.4567x; 1.0483x over previous
#include <cuda_runtime.h>
#include <cstdint>

// ---- problem constants ----
#define NB   16
#define CC   256
#define MM   63
#define MO   56
#define XPL  3969            // 63*63 floats per (n,c) plane
#define PX   4096            // padded pixel space (64x64) per sample
#define NTAP 64
#define MT   32              // 32 m-tiles of 128 pixels

// smem word layout: A frags [8 warptiles][16 kk][32 lane][4 reg] = 16384 words (64KB)
//                   B frags [16 kk][8 nf][32 lane][2 reg]       =  8192 words (32KB)
#define BBASE 16384
#define SMEMB ((16384 + 8192) * 4)       // 98304 bytes
#define DSTR  65                          // D smem row stride (floats)

// D^T scratch: [n][tap][pixel] fp32 = 16 MB, fully rewritten each launch.
__device__ float g_dt[(size_t)NB * NTAP * PX];

static __device__ __forceinline__ float fsq(float a) {
    float r; asm("sqrt.approx.f32 %0, %1;" : "=f"(r) : "f"(a)); return r;
}
// pack: low half = lo, high half = hi (cvt puts %1 in upper 16 bits)
static __device__ __forceinline__ uint32_t bpk(float lo, float hi) {
    uint32_t r;
    asm("cvt.rn.bf16x2.f32 %0, %1, %2;" : "=r"(r) : "f"(hi), "f"(lo));
    return r;
}
static __device__ __forceinline__ void mma16816(float* d, uint4 a, uint2 b) {
    asm volatile(
        "mma.sync.aligned.m16n8k16.row.col.f32.bf16.bf16.f32 "
        "{%0,%1,%2,%3}, {%4,%5,%6,%7}, {%8,%9}, {%0,%1,%2,%3};"
        : "+f"(d[0]), "+f"(d[1]), "+f"(d[2]), "+f"(d[3])
        : "r"(a.x), "r"(a.y), "r"(a.z), "r"(a.w), "r"(b.x), "r"(b.y));
}

// ============================================================
// GEMM: per sample n, D[pixel 4096][tap 64] = sum_c sqrt(x[c,pix]) *
//       (w[c]*sqrt(z[c,tap])/64), bf16 in / fp32 accum, via mma.sync.
// grid (32 mtiles, 16 n), 256 threads (8 warps; warp w owns 16 pixels).
// ============================================================
__global__ __launch_bounds__(256)
void bc_gemm(const float* __restrict__ z, const float* __restrict__ x,
             const float* __restrict__ w) {
    extern __shared__ uint32_t sm4[];
    const int u   = threadIdx.x;
    const int ell = u & 31, grp = u >> 5;        // lane, warp
    const int rl  = ell >> 2, cq = ell & 3;      // fragment row-low / col-quad
    const int mtile = blockIdx.x, n = blockIdx.y;

    const float* xn = x + (size_t)n * CC * XPL;
    const float* zn = z + (size_t)n * CC * 64;

    // ---- stage A in fragment layout (this thread feeds mma lane 'ell' of warp 'grp') ----
    {
        const int P0  = mtile * 128 + grp * 16;
        const int pxa = P0 + rl, pxb = pxa + 8;
        const int ra = pxa >> 6, sa = pxa & 63;
        const int rb = pxb >> 6, sb = pxb & 63;
        const bool va = (sa < 63) && (ra < 63);
        const bool vb = (sb < 63) && (rb < 63);
        const int pa = (ra < 63 ? ra : 62) * 63 + (sa < 63 ? sa : 62);
        const int pb = (rb < 63 ? rb : 62) * 63 + (sb < 63 ? sb : 62);
        uint32_t* adst = sm4 + grp * 2048 + ell * 4;

        #pragma unroll 4
        for (int kk = 0; kk < 16; ++kk) {
            const float* x0 = xn + (kk * 16 + cq * 2) * XPL;
            float a0 = __ldg(x0 + pa),            a1 = __ldg(x0 + XPL + pa);
            float b0 = __ldg(x0 + pb),            b1 = __ldg(x0 + XPL + pb);
            float a8 = __ldg(x0 + 8 * XPL + pa),  a9 = __ldg(x0 + 9 * XPL + pa);
            float b8 = __ldg(x0 + 8 * XPL + pb),  b9 = __ldg(x0 + 9 * XPL + pb);
            a0 = va ? fsq(a0) : 0.f;  a1 = va ? fsq(a1) : 0.f;
            a8 = va ? fsq(a8) : 0.f;  a9 = va ? fsq(a9) : 0.f;
            b0 = vb ? fsq(b0) : 0.f;  b1 = vb ? fsq(b1) : 0.f;
            b8 = vb ? fsq(b8) : 0.f;  b9 = vb ? fsq(b9) : 0.f;
            uint4 v;
            v.x = bpk(a0, a1);   // reg0: row rl,   cols c0,c0+1
            v.y = bpk(b0, b1);   // reg1: row rl+8
            v.z = bpk(a8, a9);   // reg2: row rl,   cols c0+8,c0+9
            v.w = bpk(b8, b9);   // reg3: row rl+8
            *(uint4*)(adst + kk * 128) = v;    // STS.128, conflict-free
        }
    }
    // ---- stage B in fragment layout: warp grp = n-frag grp, lane = tap/k slot ----
    {
        const int tap = grp * 8 + rl;
        const float* zt = zn + tap;
        #pragma unroll 4
        for (int kk = 0; kk < 16; ++kk) {
            const int c0 = kk * 16 + cq * 2;
            float v0 = __ldg(w + c0)     * 0.015625f * fsq(__ldg(zt + c0 * 64));
            float v1 = __ldg(w + c0 + 1) * 0.015625f * fsq(__ldg(zt + (c0 + 1) * 64));
            float v8 = __ldg(w + c0 + 8) * 0.015625f * fsq(__ldg(zt + (c0 + 8) * 64));
            float v9 = __ldg(w + c0 + 9) * 0.015625f * fsq(__ldg(zt + (c0 + 9) * 64));
            uint2 bv;
            bv.x = bpk(v0, v1);   // reg0: k = 2cq, 2cq+1
            bv.y = bpk(v8, v9);   // reg1: k = 2cq+8, 2cq+9
            *(uint2*)(sm4 + BBASE + ((kk * 8 + grp) * 32 + ell) * 2) = bv; // STS.64
        }
    }
    __syncthreads();

    // ---- MMA mainloop: 16 k-steps x 8 n-frags ----
    float acc[8][4];
    #pragma unroll
    for (int f = 0; f < 8; ++f)
        #pragma unroll
        for (int e = 0; e < 4; ++e) acc[f][e] = 0.f;
    {
        const uint32_t* aw = sm4 + grp * 2048 + ell * 4;
        const uint32_t* bw = sm4 + BBASE + ell * 2;
        #pragma unroll
        for (int kk = 0; kk < 16; ++kk) {
            uint4 a = *(const uint4*)(aw + kk * 128);        // LDS.128, conflict-free
            #pragma unroll
            for (int nf = 0; nf < 8; ++nf) {
                uint2 b = *(const uint2*)(bw + (kk * 8 + nf) * 64);  // LDS.64
                mma16816(acc[nf], a, b);
            }
        }
    }
    __syncthreads();   // A region dead; reuse as D tile

    // ---- D frags -> smem [px 128][tap 64] (stride 65) ----
    {
        float* ds = (float*)sm4;
        const int pxl = grp * 16 + rl;
        const int t0  = 2 * cq;
        #pragma unroll
        for (int nf = 0; nf < 8; ++nf) {
            const int tw = nf * 8 + t0;
            ds[pxl * DSTR + tw]           = acc[nf][0];
            ds[pxl * DSTR + tw + 1]       = acc[nf][1];
            ds[(pxl + 8) * DSTR + tw]     = acc[nf][2];
            ds[(pxl + 8) * DSTR + tw + 1] = acc[nf][3];
        }
    }
    __syncthreads();

    // ---- transposed, coalesced store: g_dt[n][tap][mtile*128 + px] ----
    {
        const float* ds = (const float*)sm4;
        const int px = u & 127, th = u >> 7;
        float* dt = g_dt + (size_t)n * NTAP * PX + mtile * 128 + px;
        #pragma unroll 8
        for (int c = 0; c < 32; ++c) {
            const int tap = th * 32 + c;
            dt[(size_t)tap * PX] = ds[px * DSTR + tap];   // LDS conflict-free, STG coalesced
        }
    }
}

// ============================================================
// Epilogue: out[n,i,j] = sum_{p,q} D^T[n][p*8+q][(i+p)*64 + (j+q)]
// grid (56, 16), 64 threads (56 active). g_dt is L2-resident (16 MB).
// ============================================================
__global__ __launch_bounds__(64)
void bc_epi(float* __restrict__ out) {
    const int i = blockIdx.x, n = blockIdx.y, j = threadIdx.x;
    if (j >= MO) return;
    const float* dn = g_dt + (size_t)n * NTAP * PX;
    float s0 = 0.f, s1 = 0.f, s2 = 0.f, s3 = 0.f;
    #pragma unroll
    for (int p = 0; p < 8; ++p) {
        const float* row = dn + (size_t)(p * 8) * PX + ((i + p) << 6) + j;
        s0 += row[0 * PX + 0];  s1 += row[1 * PX + 1];
        s2 += row[2 * PX + 2];  s3 += row[3 * PX + 3];
        s0 += row[4 * PX + 4];  s1 += row[5 * PX + 5];
        s2 += row[6 * PX + 6];  s3 += row[7 * PX + 7];
    }
    out[((size_t)n * MO + i) * MO + j] = (s0 + s1) + (s2 + s3);
}

// ---------- launch ----------
// Two launches only (the 3 nop pads cost ~3us each as graph nodes — measured
// in R14's profile — and were removed). ncu empirically captures 0-based
// launch index 3 => bc_epi (call 2) gets profiled this round.
extern "C" void kernel_launch(void* const* d_in, const int* in_sizes, int n_in,
                              void* d_out, int out_size) {
    const float* z = (const float*)d_in[0];   // (16,256,8,8)
    const float* x = (const float*)d_in[1];   // (16,256,63,63)
    const float* w = (const float*)d_in[2];   // 256 weights
    float* out = (float*)d_out;               // (16,1,56,56)

    cudaFuncSetAttribute(bc_gemm, cudaFuncAttributeMaxDynamicSharedMemorySize, SMEMB);
    bc_gemm<<<dim3(MT, NB), 256, SMEMB>>>(z, x, w);
    bc_epi<<<dim3(MO, NB), 64>>>(out);
}